// round 2
// baseline (speedup 1.0000x reference)
#include <cuda_runtime.h>
#include <math.h>
#include <stdint.h>
#include <stddef.h>

#define B_ 2
#define S_ 2048
#define H_ 16
#define HD_ 64
#define D_ 1024
#define BH_ (B_*H_)
#define NKEEP 675
#define MASKV -10000.0f

// ---------------- scratch (static device allocations are allowed) -------------
__device__ float g_q[(size_t)BH_*S_*HD_];
__device__ float g_k[(size_t)BH_*S_*HD_];
__device__ float g_v[(size_t)BH_*S_*HD_];
__device__ float g_oh[(size_t)B_*S_*D_];
__device__ float g_sq[BH_*S_];
__device__ float g_d2c[BH_*S_];
__device__ float g_mmd[BH_*S_];
__device__ unsigned char g_land[BH_*S_];

// ---------------- generic SGEMM: C[M][N] = A[M][1024] * Bw[N][1024]^T + bias --
// MODE 0: plain write to C. MODE 1: scatter into g_q/g_k/g_v (qkv layout).
template<int MODE>
__global__ __launch_bounds__(256) void gemm_kernel(const float* __restrict__ A,
                                                   const float* __restrict__ Bw,
                                                   const float* __restrict__ bias,
                                                   float* __restrict__ C, int N) {
    const int K = 1024;
    __shared__ float As[16][129];
    __shared__ float Bs[16][129];
    int bm = blockIdx.y * 128, bn = blockIdx.x * 128;
    int tid = threadIdx.x;
    int ty = tid >> 4, tx = tid & 15;
    float acc[8][8];
#pragma unroll
    for (int i = 0; i < 8; i++)
#pragma unroll
        for (int j = 0; j < 8; j++) acc[i][j] = 0.f;
    const float4* A4 = (const float4*)A;
    const float4* B4 = (const float4*)Bw;
    for (int k0 = 0; k0 < K; k0 += 16) {
#pragma unroll
        for (int u = 0; u < 2; u++) {
            int fi = tid + 256 * u;
            int row = fi >> 2, k4 = fi & 3;
            float4 va = A4[(size_t)(bm + row) * (K / 4) + (k0 >> 2) + k4];
            As[k4 * 4 + 0][row] = va.x; As[k4 * 4 + 1][row] = va.y;
            As[k4 * 4 + 2][row] = va.z; As[k4 * 4 + 3][row] = va.w;
            float4 vb = B4[(size_t)(bn + row) * (K / 4) + (k0 >> 2) + k4];
            Bs[k4 * 4 + 0][row] = vb.x; Bs[k4 * 4 + 1][row] = vb.y;
            Bs[k4 * 4 + 2][row] = vb.z; Bs[k4 * 4 + 3][row] = vb.w;
        }
        __syncthreads();
#pragma unroll
        for (int kk = 0; kk < 16; kk++) {
            float a[8], b[8];
#pragma unroll
            for (int i = 0; i < 8; i++) a[i] = As[kk][ty + 16 * i];
#pragma unroll
            for (int j = 0; j < 8; j++) b[j] = Bs[kk][tx + 16 * j];
#pragma unroll
            for (int i = 0; i < 8; i++)
#pragma unroll
                for (int j = 0; j < 8; j++) acc[i][j] += a[i] * b[j];
        }
        __syncthreads();
    }
#pragma unroll
    for (int i = 0; i < 8; i++) {
        int m = bm + ty + 16 * i;
#pragma unroll
        for (int j = 0; j < 8; j++) {
            int n = bn + tx + 16 * j;
            float v = acc[i][j] + bias[n];
            if (MODE == 0) {
                C[(size_t)m * N + n] = v;
            } else {
                int which = n >> 10;
                int h = (n & 1023) >> 6;
                int d = n & 63;
                int b = m >> 11;
                int s = m & 2047;
                float* dst = (which == 0) ? g_q : ((which == 1) ? g_k : g_v);
                dst[(((size_t)b * H_ + h) * S_ + s) * HD_ + d] = v;
            }
        }
    }
}

// ---------------- centroid + d2c + squared norms per (b,h) -------------------
__global__ __launch_bounds__(256) void stats_kernel(const float* __restrict__ x) {
    int bh = blockIdx.x;
    int b = bh >> 4, h = bh & 15;
    const float* xb = x + (size_t)b * S_ * D_ + h * 64;
    __shared__ float cen[64];
    __shared__ float part[4][64];
    int tid = threadIdx.x;
    int d = tid & 63, g = tid >> 6;
    float s = 0.f;
    for (int srow = g; srow < S_; srow += 4)
        s += xb[(size_t)srow * D_ + d];
    part[g][d] = s;
    __syncthreads();
    if (tid < 64)
        cen[tid] = (part[0][tid] + part[1][tid] + part[2][tid] + part[3][tid]) * (1.0f / 2048.0f);
    __syncthreads();
    for (int srow = tid; srow < S_; srow += 256) {
        const float4* xr = (const float4*)(xb + (size_t)srow * D_);
        float sq = 0.f, dd = 0.f;
#pragma unroll
        for (int u = 0; u < 16; u++) {
            float4 v = xr[u];
            sq += v.x * v.x + v.y * v.y + v.z * v.z + v.w * v.w;
            float a0 = v.x - cen[4 * u + 0];
            float a1 = v.y - cen[4 * u + 1];
            float a2 = v.z - cen[4 * u + 2];
            float a3 = v.w - cen[4 * u + 3];
            dd += a0 * a0 + a1 * a1 + a2 * a2 + a3 * a3;
        }
        g_sq[bh * S_ + srow] = sq;
        g_d2c[bh * S_ + srow] = sqrtf(dd);
    }
}

#define DOT4(a, b) ((a).x*(b).x + (a).y*(b).y + (a).z*(b).z + (a).w*(b).w)

// ---------------- 10-NN distance kernel: mmd = 10th smallest pairwise dist ---
#define KNN_SMEM (16*2048*4 + 16*64*4 + 128*68*4 + 2048*4)
__global__ __launch_bounds__(256) void knn_kernel(const float* __restrict__ x) {
    extern __shared__ float sm[];
    float* Ss = sm;                 // 16 x 2048
    float* Is = sm + 16 * 2048;     // 16 x 64
    float* KV = Is + 16 * 64;       // 128 x 68
    float* sqs = KV + 128 * 68;     // 2048
    int bx = blockIdx.x;
    int it = bx & 127, bh = bx >> 7;
    int b = bh >> 4, h = bh & 15;
    const float* xb = x + (size_t)b * S_ * D_ + h * 64;
    int tid = threadIdx.x;
    int ibase = it << 4;
    {
        int r = tid >> 4, d4 = tid & 15;
        const float4* p = (const float4*)(xb + (size_t)(ibase + r) * D_);
        *(float4*)&Is[r * 64 + d4 * 4] = p[d4];
    }
    for (int l = tid; l < S_; l += 256) sqs[l] = g_sq[bh * S_ + l];
    __syncthreads();
    int ty = tid >> 5, tx = tid & 31;
    for (int jt = 0; jt < 16; jt++) {
        int jb = jt << 7;
        __syncthreads();
#pragma unroll
        for (int u = 0; u < 8; u++) {
            int fi = tid + 256 * u;
            int kc = fi >> 4, d4 = fi & 15;
            const float4* p = (const float4*)(xb + (size_t)(jb + kc) * D_);
            *(float4*)&KV[kc * 68 + d4 * 4] = p[d4];
        }
        __syncthreads();
        float acc[2][4];
#pragma unroll
        for (int i = 0; i < 2; i++)
#pragma unroll
            for (int j = 0; j < 4; j++) acc[i][j] = 0.f;
#pragma unroll 4
        for (int d4 = 0; d4 < 16; d4++) {
            float4 a0 = *(const float4*)&Is[ty * 64 + d4 * 4];
            float4 a1 = *(const float4*)&Is[(ty + 8) * 64 + d4 * 4];
            float4 b0 = *(const float4*)&KV[(tx) * 68 + d4 * 4];
            float4 b1 = *(const float4*)&KV[(tx + 32) * 68 + d4 * 4];
            float4 b2 = *(const float4*)&KV[(tx + 64) * 68 + d4 * 4];
            float4 b3 = *(const float4*)&KV[(tx + 96) * 68 + d4 * 4];
            acc[0][0] += DOT4(a0, b0); acc[0][1] += DOT4(a0, b1);
            acc[0][2] += DOT4(a0, b2); acc[0][3] += DOT4(a0, b3);
            acc[1][0] += DOT4(a1, b0); acc[1][1] += DOT4(a1, b1);
            acc[1][2] += DOT4(a1, b2); acc[1][3] += DOT4(a1, b3);
        }
#pragma unroll
        for (int i = 0; i < 2; i++)
#pragma unroll
            for (int j = 0; j < 4; j++) {
                int r = ty + 8 * i, c = tx + 32 * j;
                int gi = ibase + r, gj = jb + c;
                float d2 = sqs[gi] + sqs[gj] - 2.0f * acc[i][j];
                Ss[r * 2048 + gj] = sqrtf(fmaxf(d2, 0.f));
            }
    }
    __syncthreads();
    // top-10 smallest per row; warp ty handles rows ty, ty+8
    for (int rr = 0; rr < 2; rr++) {
        int r = ty + 8 * rr;
        float lst[10];
#pragma unroll
        for (int u = 0; u < 10; u++) lst[u] = 3.0e38f;
        for (int t = 0; t < 64; t++) {
            float dv = Ss[r * 2048 + tx + 32 * t];
            if (dv < lst[9]) {
                lst[9] = dv;
#pragma unroll
                for (int u = 9; u > 0; u--) {
                    float lo = lst[u - 1];
                    if (lst[u] < lo) { lst[u - 1] = lst[u]; lst[u] = lo; }
                }
            }
        }
        float kth = 0.f;
#pragma unroll
        for (int round = 0; round < 10; round++) {
            float v = lst[0]; int l = tx;
#pragma unroll
            for (int o = 16; o; o >>= 1) {
                float vo = __shfl_down_sync(0xffffffffu, v, o);
                int lo = __shfl_down_sync(0xffffffffu, l, o);
                if (vo < v) { v = vo; l = lo; }
            }
            v = __shfl_sync(0xffffffffu, v, 0);
            l = __shfl_sync(0xffffffffu, l, 0);
            if (tx == l) {
#pragma unroll
                for (int u = 0; u < 9; u++) lst[u] = lst[u + 1];
                lst[9] = 3.0e38f;
            }
            kth = v;
        }
        if (tx == 0) g_mmd[bh * S_ + ibase + r] = kth;
    }
}

// ---------------- tls + exact top-675 selection (jax top_k tie order) --------
__device__ __forceinline__ unsigned fkey(float f) {
    unsigned u = __float_as_uint(f);
    return (u & 0x80000000u) ? ~u : (u | 0x80000000u);
}

__global__ __launch_bounds__(256) void tls_kernel() {
    __shared__ unsigned keys[S_];
    __shared__ float wred[8];
    __shared__ int wcnt[8];
    __shared__ float bcast[2];
    __shared__ int cntb;
    int bh = blockIdx.x;
    int tid = threadIdx.x, lane = tid & 31, w = tid >> 5;
    float md = -1e30f, mm = -1e30f;
    for (int s = tid; s < S_; s += 256) {
        md = fmaxf(md, g_d2c[bh * S_ + s]);
        mm = fmaxf(mm, g_mmd[bh * S_ + s]);
    }
#pragma unroll
    for (int o = 16; o; o >>= 1) {
        md = fmaxf(md, __shfl_xor_sync(0xffffffffu, md, o));
        mm = fmaxf(mm, __shfl_xor_sync(0xffffffffu, mm, o));
    }
    if (lane == 0) wred[w] = md;
    __syncthreads();
    if (tid == 0) { float v = wred[0]; for (int i = 1; i < 8; i++) v = fmaxf(v, wred[i]); bcast[0] = v; }
    __syncthreads();
    if (lane == 0) wred[w] = mm;
    __syncthreads();
    if (tid == 0) { float v = wred[0]; for (int i = 1; i < 8; i++) v = fmaxf(v, wred[i]); bcast[1] = v; }
    __syncthreads();
    float dmax = bcast[0] + 1e-8f, mmax = bcast[1] + 1e-8f;
    for (int s = tid; s < S_; s += 256) {
        float t = 0.7f * (g_d2c[bh * S_ + s] / dmax) + 0.3f * (g_mmd[bh * S_ + s] / mmax);
        keys[s] = fkey(t);
    }
    __syncthreads();
    unsigned prefix = 0;
    for (int bit = 31; bit >= 0; bit--) {
        unsigned cand = prefix | (1u << bit);
        int c = 0;
        for (int s = tid; s < S_; s += 256) c += (keys[s] >= cand) ? 1 : 0;
#pragma unroll
        for (int o = 16; o; o >>= 1) c += __shfl_xor_sync(0xffffffffu, c, o);
        if (lane == 0) wcnt[w] = c;
        __syncthreads();
        if (tid == 0) { int t = 0; for (int i = 0; i < 8; i++) t += wcnt[i]; cntb = t; }
        __syncthreads();
        if (cntb >= NKEEP) prefix = cand;
        __syncthreads();
    }
    {
        int c = 0;
        for (int s = tid; s < S_; s += 256) c += (keys[s] > prefix) ? 1 : 0;
#pragma unroll
        for (int o = 16; o; o >>= 1) c += __shfl_xor_sync(0xffffffffu, c, o);
        if (lane == 0) wcnt[w] = c;
        __syncthreads();
        if (tid == 0) {
            int t = 0; for (int i = 0; i < 8; i++) t += wcnt[i];
            int quota = NKEEP - t;
            for (int s = 0; s < S_; s++) {
                unsigned kk = keys[s];
                unsigned char mv = 0;
                if (kk > prefix) mv = 1;
                else if (kk == prefix && quota > 0) { mv = 1; quota--; }
                g_land[bh * S_ + s] = mv;
            }
        }
    }
}

// ---------------- attention: scores -> masked softmax -> attn write + AV -----
#define ATTN_SMEM (16*2048*4 + 16*64*4 + 128*68*4 + 2048)
__global__ __launch_bounds__(256) void attn_kernel(float* __restrict__ attn_out) {
    extern __shared__ float sm[];
    float* Ss = sm;                   // 16 x 2048 scores/probs
    float* Qs = sm + 16 * 2048;       // 16 x 64
    float* KV = Qs + 16 * 64;         // 128 x 68 (K tiles, then V tiles)
    unsigned char* Lm = (unsigned char*)(KV + 128 * 68);  // 2048
    int bx = blockIdx.x;
    int qt = bx & 127, bh = bx >> 7;
    int qbase = qt << 4;
    size_t base = (size_t)bh * S_ * HD_;
    const float4* Qg = (const float4*)(g_q + base);
    const float4* Kg = (const float4*)(g_k + base);
    const float4* Vg = (const float4*)(g_v + base);
    int tid = threadIdx.x;
    {
        int r = tid >> 4, d4 = tid & 15;
        *(float4*)&Qs[r * 64 + d4 * 4] = Qg[(size_t)(qbase + r) * 16 + d4];
    }
    for (int l = tid; l < S_; l += 256) Lm[l] = g_land[bh * S_ + l];
    __syncthreads();
    int ty = tid >> 5, tx = tid & 31;
    // ---- scores ----
    for (int kt = 0; kt < 16; kt++) {
        int kb = kt << 7;
        __syncthreads();
#pragma unroll
        for (int u = 0; u < 8; u++) {
            int fi = tid + 256 * u;
            int kc = fi >> 4, d4 = fi & 15;
            *(float4*)&KV[kc * 68 + d4 * 4] = Kg[(size_t)(kb + kc) * 16 + d4];
        }
        __syncthreads();
        float acc[2][4];
#pragma unroll
        for (int i = 0; i < 2; i++)
#pragma unroll
            for (int j = 0; j < 4; j++) acc[i][j] = 0.f;
#pragma unroll 4
        for (int d4 = 0; d4 < 16; d4++) {
            float4 a0 = *(const float4*)&Qs[ty * 64 + d4 * 4];
            float4 a1 = *(const float4*)&Qs[(ty + 8) * 64 + d4 * 4];
            float4 b0 = *(const float4*)&KV[(tx) * 68 + d4 * 4];
            float4 b1 = *(const float4*)&KV[(tx + 32) * 68 + d4 * 4];
            float4 b2 = *(const float4*)&KV[(tx + 64) * 68 + d4 * 4];
            float4 b3 = *(const float4*)&KV[(tx + 96) * 68 + d4 * 4];
            acc[0][0] += DOT4(a0, b0); acc[0][1] += DOT4(a0, b1);
            acc[0][2] += DOT4(a0, b2); acc[0][3] += DOT4(a0, b3);
            acc[1][0] += DOT4(a1, b0); acc[1][1] += DOT4(a1, b1);
            acc[1][2] += DOT4(a1, b2); acc[1][3] += DOT4(a1, b3);
        }
#pragma unroll
        for (int i = 0; i < 2; i++)
#pragma unroll
            for (int j = 0; j < 4; j++) {
                int r = ty + 8 * i, c = tx + 32 * j;
                int gq = qbase + r, gj = kb + c;
                int rel = gj - gq;
                bool keep = (rel >= -64 && rel <= 64) || (Lm[gj] != 0);
                Ss[r * 2048 + gj] = keep ? acc[i][j] * 0.125f : MASKV;
            }
    }
    __syncthreads();
    // ---- softmax per row; warp ty owns rows ty and ty+8 ----
    for (int rr = 0; rr < 2; rr++) {
        int r = ty + 8 * rr;
        int gq = qbase + r;
        float m = -3.0e38f;
        for (int t = 0; t < 64; t++) m = fmaxf(m, Ss[r * 2048 + tx + 32 * t]);
#pragma unroll
        for (int o = 16; o; o >>= 1) m = fmaxf(m, __shfl_xor_sync(0xffffffffu, m, o));
        float sum = 0.f;
        for (int t = 0; t < 64; t++) {
            int c = tx + 32 * t;
            float e = __expf(Ss[r * 2048 + c] - m);
            Ss[r * 2048 + c] = e;
            sum += e;
        }
#pragma unroll
        for (int o = 16; o; o >>= 1) sum += __shfl_xor_sync(0xffffffffu, sum, o);
        float is = 1.0f / sum;
        float* arow = attn_out ? (attn_out + ((size_t)bh * S_ + gq) * S_) : (float*)0;
        for (int t = 0; t < 64; t++) {
            int c = tx + 32 * t;
            float p = Ss[r * 2048 + c] * is;
            Ss[r * 2048 + c] = p;
            if (arow) arow[c] = p;
        }
    }
    // ---- AV ----
    float o00 = 0.f, o01 = 0.f, o10 = 0.f, o11 = 0.f;
    for (int vt = 0; vt < 16; vt++) {
        int vb = vt << 7;
        __syncthreads();
#pragma unroll
        for (int u = 0; u < 8; u++) {
            int fi = tid + 256 * u;
            int kc = fi >> 4, d4 = fi & 15;
            *(float4*)&KV[kc * 68 + d4 * 4] = Vg[(size_t)(vb + kc) * 16 + d4];
        }
        __syncthreads();
#pragma unroll 4
        for (int kc = 0; kc < 128; kc++) {
            float p0 = Ss[(ty) * 2048 + vb + kc];
            float p1 = Ss[(ty + 8) * 2048 + vb + kc];
            float v0 = KV[kc * 68 + tx];
            float v1 = KV[kc * 68 + tx + 32];
            o00 += p0 * v0; o01 += p0 * v1;
            o10 += p1 * v0; o11 += p1 * v1;
        }
    }
    int b = bh >> 4, h = bh & 15;
    g_oh[(((size_t)b * S_ + qbase + ty) * H_ + h) * HD_ + tx] = o00;
    g_oh[(((size_t)b * S_ + qbase + ty) * H_ + h) * HD_ + tx + 32] = o01;
    g_oh[(((size_t)b * S_ + qbase + ty + 8) * H_ + h) * HD_ + tx] = o10;
    g_oh[(((size_t)b * S_ + qbase + ty + 8) * H_ + h) * HD_ + tx + 32] = o11;
}

// ---------------- launch ------------------------------------------------------
extern "C" void kernel_launch(void* const* d_in, const int* in_sizes, int n_in,
                              void* d_out, int out_size) {
    const float* x     = (const float*)d_in[0];
    const float* qkv_w = (const float*)d_in[1];
    const float* qkv_b = (const float*)d_in[2];
    const float* out_w = (const float*)d_in[3];
    const float* out_b = (const float*)d_in[4];
    float* out = (float*)d_out;
    const long long out_elems = (long long)B_ * S_ * D_;                  // 4194304
    const long long attn_elems = (long long)B_ * H_ * S_ * S_;            // 134217728
    float* attn = ((long long)out_size >= out_elems + attn_elems) ? (out + out_elems) : (float*)0;

    cudaFuncSetAttribute(attn_kernel, cudaFuncAttributeMaxDynamicSharedMemorySize, ATTN_SMEM);
    cudaFuncSetAttribute(knn_kernel, cudaFuncAttributeMaxDynamicSharedMemorySize, KNN_SMEM);

    void* ohp = 0;
    cudaGetSymbolAddress(&ohp, g_oh);

    gemm_kernel<1><<<dim3(24, 32), 256>>>(x, qkv_w, qkv_b, (float*)0, 3072);
    stats_kernel<<<32, 256>>>(x);
    knn_kernel<<<4096, 256, KNN_SMEM>>>(x);
    tls_kernel<<<32, 256>>>();
    attn_kernel<<<4096, 256, ATTN_SMEM>>>(attn);
    gemm_kernel<0><<<dim3(8, 32), 256>>>((const float*)ohp, out_w, out_b, out, 1024);
}

// round 3
// speedup vs baseline: 1.3674x; 1.3674x over previous
#include <cuda_runtime.h>
#include <math.h>
#include <stdint.h>
#include <stddef.h>

#define B_ 2
#define S_ 2048
#define H_ 16
#define HD_ 64
#define D_ 1024
#define BH_ (B_*H_)
#define NKEEP 675
#define MASKV -10000.0f

// ---------------- scratch -----------------------------------------------------
__device__ float g_q[(size_t)BH_*S_*HD_];
__device__ float g_k[(size_t)BH_*S_*HD_];
__device__ float g_v[(size_t)BH_*S_*HD_];
__device__ float g_oh[(size_t)B_*S_*D_];
__device__ float g_sq[BH_*S_];
__device__ float g_d2c[BH_*S_];
__device__ float g_mmd[BH_*S_];
__device__ unsigned char g_land[BH_*S_];
__device__ int g_lidx[BH_*NKEEP];

// ---------------- generic SGEMM: C[M][N] = A[M][1024] * Bw[N][1024]^T + bias --
template<int MODE>
__global__ __launch_bounds__(256) void gemm_kernel(const float* __restrict__ A,
                                                   const float* __restrict__ Bw,
                                                   const float* __restrict__ bias,
                                                   float* __restrict__ C, int N) {
    const int K = 1024;
    __shared__ float As[16][129];
    __shared__ float Bs[16][129];
    int bm = blockIdx.y * 128, bn = blockIdx.x * 128;
    int tid = threadIdx.x;
    int ty = tid >> 4, tx = tid & 15;
    float acc[8][8];
#pragma unroll
    for (int i = 0; i < 8; i++)
#pragma unroll
        for (int j = 0; j < 8; j++) acc[i][j] = 0.f;
    const float4* A4 = (const float4*)A;
    const float4* B4 = (const float4*)Bw;
    for (int k0 = 0; k0 < K; k0 += 16) {
#pragma unroll
        for (int u = 0; u < 2; u++) {
            int fi = tid + 256 * u;
            int row = fi >> 2, k4 = fi & 3;
            float4 va = A4[(size_t)(bm + row) * (K / 4) + (k0 >> 2) + k4];
            As[k4 * 4 + 0][row] = va.x; As[k4 * 4 + 1][row] = va.y;
            As[k4 * 4 + 2][row] = va.z; As[k4 * 4 + 3][row] = va.w;
            float4 vb = B4[(size_t)(bn + row) * (K / 4) + (k0 >> 2) + k4];
            Bs[k4 * 4 + 0][row] = vb.x; Bs[k4 * 4 + 1][row] = vb.y;
            Bs[k4 * 4 + 2][row] = vb.z; Bs[k4 * 4 + 3][row] = vb.w;
        }
        __syncthreads();
#pragma unroll
        for (int kk = 0; kk < 16; kk++) {
            float a[8], b[8];
#pragma unroll
            for (int i = 0; i < 8; i++) a[i] = As[kk][ty + 16 * i];
#pragma unroll
            for (int j = 0; j < 8; j++) b[j] = Bs[kk][tx + 16 * j];
#pragma unroll
            for (int i = 0; i < 8; i++)
#pragma unroll
                for (int j = 0; j < 8; j++) acc[i][j] += a[i] * b[j];
        }
        __syncthreads();
    }
#pragma unroll
    for (int i = 0; i < 8; i++) {
        int m = bm + ty + 16 * i;
#pragma unroll
        for (int j = 0; j < 8; j++) {
            int n = bn + tx + 16 * j;
            float v = acc[i][j] + bias[n];
            if (MODE == 0) {
                C[(size_t)m * N + n] = v;
            } else {
                int which = n >> 10;
                int h = (n & 1023) >> 6;
                int d = n & 63;
                int b = m >> 11;
                int s = m & 2047;
                float* dst = (which == 0) ? g_q : ((which == 1) ? g_k : g_v);
                dst[(((size_t)b * H_ + h) * S_ + s) * HD_ + d] = v;
            }
        }
    }
}

// ---------------- centroid + d2c + squared norms per (b,h) -------------------
__global__ __launch_bounds__(256) void stats_kernel(const float* __restrict__ x) {
    int bh = blockIdx.x;
    int b = bh >> 4, h = bh & 15;
    const float* xb = x + (size_t)b * S_ * D_ + h * 64;
    __shared__ float cen[64];
    __shared__ float part[4][64];
    int tid = threadIdx.x;
    int d = tid & 63, g = tid >> 6;
    float s = 0.f;
    for (int srow = g; srow < S_; srow += 4)
        s += xb[(size_t)srow * D_ + d];
    part[g][d] = s;
    __syncthreads();
    if (tid < 64)
        cen[tid] = (part[0][tid] + part[1][tid] + part[2][tid] + part[3][tid]) * (1.0f / 2048.0f);
    __syncthreads();
    for (int srow = tid; srow < S_; srow += 256) {
        const float4* xr = (const float4*)(xb + (size_t)srow * D_);
        float sq = 0.f, dd = 0.f;
#pragma unroll
        for (int u = 0; u < 16; u++) {
            float4 v = xr[u];
            sq += v.x * v.x + v.y * v.y + v.z * v.z + v.w * v.w;
            float a0 = v.x - cen[4 * u + 0];
            float a1 = v.y - cen[4 * u + 1];
            float a2 = v.z - cen[4 * u + 2];
            float a3 = v.w - cen[4 * u + 3];
            dd += a0 * a0 + a1 * a1 + a2 * a2 + a3 * a3;
        }
        g_sq[bh * S_ + srow] = sq;
        g_d2c[bh * S_ + srow] = sqrtf(dd);
    }
}

#define DOT4(a, b) ((a).x*(b).x + (a).y*(b).y + (a).z*(b).z + (a).w*(b).w)

// ---------------- 10-NN: mmd = sqrt(10th smallest pairwise squared dist) -----
#define KNN_SMEM (131072 + 69632 + 4096 + 8192)
__global__ __launch_bounds__(256) void knn_kernel(const float* __restrict__ x) {
    extern __shared__ float sm[];
    float* Ss = sm;                     // 16 x 2048 (d2 values)
    float* KV = sm + 16 * 2048;         // 256 x 68
    float* Is = KV + 256 * 68;          // 16 x 64
    float* sqs = Is + 16 * 64;          // 2048
    int bx = blockIdx.x;
    int it = bx & 127, bh = bx >> 7;
    int b = bh >> 4, h = bh & 15;
    const float* xb = x + (size_t)b * S_ * D_ + h * 64;
    int tid = threadIdx.x;
    int ibase = it << 4;
    {
        int r = tid >> 4, d4 = tid & 15;
        const float4* p = (const float4*)(xb + (size_t)(ibase + r) * D_);
        *(float4*)&Is[r * 64 + d4 * 4] = p[d4];
    }
    for (int l = tid; l < S_; l += 256) sqs[l] = g_sq[bh * S_ + l];
    int rg = tid >> 6, cg = tid & 63;
    for (int jt = 0; jt < 8; jt++) {
        int jb = jt << 8;
        __syncthreads();
#pragma unroll
        for (int u = 0; u < 16; u++) {
            int fi = tid + 256 * u;
            int jj = fi >> 4, d4 = fi & 15;
            const float4* p = (const float4*)(xb + (size_t)(jb + jj) * D_);
            *(float4*)&KV[jj * 68 + d4 * 4] = p[d4];
        }
        __syncthreads();
        float acc[4][4];
#pragma unroll
        for (int i = 0; i < 4; i++)
#pragma unroll
            for (int j = 0; j < 4; j++) acc[i][j] = 0.f;
#pragma unroll 4
        for (int d4 = 0; d4 < 16; d4++) {
            float4 q0 = *(const float4*)&Is[(rg * 4 + 0) * 64 + d4 * 4];
            float4 q1 = *(const float4*)&Is[(rg * 4 + 1) * 64 + d4 * 4];
            float4 q2 = *(const float4*)&Is[(rg * 4 + 2) * 64 + d4 * 4];
            float4 q3 = *(const float4*)&Is[(rg * 4 + 3) * 64 + d4 * 4];
            float4 k0 = *(const float4*)&KV[(cg + 0) * 68 + d4 * 4];
            float4 k1 = *(const float4*)&KV[(cg + 64) * 68 + d4 * 4];
            float4 k2 = *(const float4*)&KV[(cg + 128) * 68 + d4 * 4];
            float4 k3 = *(const float4*)&KV[(cg + 192) * 68 + d4 * 4];
            acc[0][0] += DOT4(q0, k0); acc[0][1] += DOT4(q0, k1);
            acc[0][2] += DOT4(q0, k2); acc[0][3] += DOT4(q0, k3);
            acc[1][0] += DOT4(q1, k0); acc[1][1] += DOT4(q1, k1);
            acc[1][2] += DOT4(q1, k2); acc[1][3] += DOT4(q1, k3);
            acc[2][0] += DOT4(q2, k0); acc[2][1] += DOT4(q2, k1);
            acc[2][2] += DOT4(q2, k2); acc[2][3] += DOT4(q2, k3);
            acc[3][0] += DOT4(q3, k0); acc[3][1] += DOT4(q3, k1);
            acc[3][2] += DOT4(q3, k2); acc[3][3] += DOT4(q3, k3);
        }
#pragma unroll
        for (int i = 0; i < 4; i++)
#pragma unroll
            for (int j = 0; j < 4; j++) {
                int r = rg * 4 + i;
                int gj = jb + cg + 64 * j;
                Ss[r * 2048 + gj] = sqs[ibase + r] + sqs[gj] - 2.0f * acc[i][j];
            }
    }
    __syncthreads();
    // top-10 smallest d2 per row; warp ty handles rows ty, ty+8
    int ty = tid >> 5, tx = tid & 31;
    for (int rr = 0; rr < 2; rr++) {
        int r = ty + 8 * rr;
        float lst[10];
#pragma unroll
        for (int u = 0; u < 10; u++) lst[u] = 3.0e38f;
        for (int t = 0; t < 64; t++) {
            float dv = Ss[r * 2048 + tx + 32 * t];
            if (dv < lst[9]) {
                lst[9] = dv;
#pragma unroll
                for (int u = 9; u > 0; u--) {
                    float lo = lst[u - 1];
                    if (lst[u] < lo) { lst[u - 1] = lst[u]; lst[u] = lo; }
                }
            }
        }
        float kth = 0.f;
#pragma unroll
        for (int round = 0; round < 10; round++) {
            float v = lst[0]; int l = tx;
#pragma unroll
            for (int o = 16; o; o >>= 1) {
                float vo = __shfl_down_sync(0xffffffffu, v, o);
                int lo = __shfl_down_sync(0xffffffffu, l, o);
                if (vo < v) { v = vo; l = lo; }
            }
            v = __shfl_sync(0xffffffffu, v, 0);
            l = __shfl_sync(0xffffffffu, l, 0);
            if (tx == l) {
#pragma unroll
                for (int u = 0; u < 9; u++) lst[u] = lst[u + 1];
                lst[9] = 3.0e38f;
            }
            kth = v;
        }
        if (tx == 0) g_mmd[bh * S_ + ibase + r] = sqrtf(fmaxf(kth, 0.f));
    }
}

// ---------------- tls + exact top-675 selection + sorted landmark list -------
__device__ __forceinline__ unsigned fkey(float f) {
    unsigned u = __float_as_uint(f);
    return (u & 0x80000000u) ? ~u : (u | 0x80000000u);
}

__global__ __launch_bounds__(256) void tls_kernel() {
    __shared__ unsigned keys[S_];
    __shared__ float wred[8];
    __shared__ int wcnt_[8];
    __shared__ float bcast[2];
    __shared__ int cntb;
    __shared__ unsigned char mv[S_];
    __shared__ int eqlist[S_];
    __shared__ int eqcnt;
    __shared__ int cnts[256];
    int bh = blockIdx.x;
    int tid = threadIdx.x, lane = tid & 31, w = tid >> 5;
    float md = -1e30f, mm = -1e30f;
    for (int s = tid; s < S_; s += 256) {
        md = fmaxf(md, g_d2c[bh * S_ + s]);
        mm = fmaxf(mm, g_mmd[bh * S_ + s]);
    }
#pragma unroll
    for (int o = 16; o; o >>= 1) {
        md = fmaxf(md, __shfl_xor_sync(0xffffffffu, md, o));
        mm = fmaxf(mm, __shfl_xor_sync(0xffffffffu, mm, o));
    }
    if (lane == 0) wred[w] = md;
    __syncthreads();
    if (tid == 0) { float v = wred[0]; for (int i = 1; i < 8; i++) v = fmaxf(v, wred[i]); bcast[0] = v; }
    __syncthreads();
    if (lane == 0) wred[w] = mm;
    __syncthreads();
    if (tid == 0) { float v = wred[0]; for (int i = 1; i < 8; i++) v = fmaxf(v, wred[i]); bcast[1] = v; }
    __syncthreads();
    float dmax = bcast[0] + 1e-8f, mmax = bcast[1] + 1e-8f;
    for (int s = tid; s < S_; s += 256) {
        float t = 0.7f * (g_d2c[bh * S_ + s] / dmax) + 0.3f * (g_mmd[bh * S_ + s] / mmax);
        keys[s] = fkey(t);
    }
    __syncthreads();
    unsigned prefix = 0;
    for (int bit = 31; bit >= 0; bit--) {
        unsigned cand = prefix | (1u << bit);
        int c = 0;
        for (int s = tid; s < S_; s += 256) c += (keys[s] >= cand) ? 1 : 0;
#pragma unroll
        for (int o = 16; o; o >>= 1) c += __shfl_xor_sync(0xffffffffu, c, o);
        if (lane == 0) wcnt_[w] = c;
        __syncthreads();
        if (tid == 0) { int t = 0; for (int i = 0; i < 8; i++) t += wcnt_[i]; cntb = t; }
        __syncthreads();
        if (cntb >= NKEEP) prefix = cand;
        __syncthreads();
    }
    // count strictly-greater
    {
        int c = 0;
        for (int s = tid; s < S_; s += 256) c += (keys[s] > prefix) ? 1 : 0;
#pragma unroll
        for (int o = 16; o; o >>= 1) c += __shfl_xor_sync(0xffffffffu, c, o);
        if (lane == 0) wcnt_[w] = c;
        __syncthreads();
        if (tid == 0) { int t = 0; for (int i = 0; i < 8; i++) t += wcnt_[i]; cntb = t; eqcnt = 0; }
        __syncthreads();
    }
    for (int s = tid; s < S_; s += 256) {
        unsigned kk = keys[s];
        mv[s] = (kk > prefix) ? (unsigned char)1 : (unsigned char)0;
        if (kk == prefix) { int p = atomicAdd(&eqcnt, 1); eqlist[p] = s; }
    }
    __syncthreads();
    if (tid == 0) {
        int quota = NKEEP - cntb;
        int n = eqcnt;
        for (int q = 0; q < quota; q++) {
            int best = 0x7fffffff, bp = -1;
            for (int i = 0; i < n; i++) if (eqlist[i] < best) { best = eqlist[i]; bp = i; }
            mv[best] = 1; eqlist[bp] = 0x7fffffff;
        }
    }
    __syncthreads();
    for (int s = tid; s < S_; s += 256) g_land[bh * S_ + s] = mv[s];
    // sorted landmark index list: thread t owns s in [8t, 8t+8)
    int cnt = 0;
#pragma unroll
    for (int u = 0; u < 8; u++) cnt += mv[tid * 8 + u];
    cnts[tid] = cnt;
    __syncthreads();
    if (tid == 0) {
        int run = 0;
        for (int i = 0; i < 256; i++) { int t = cnts[i]; cnts[i] = run; run += t; }
    }
    __syncthreads();
    int o = cnts[tid];
#pragma unroll
    for (int u = 0; u < 8; u++) {
        int s = tid * 8 + u;
        if (mv[s]) g_lidx[bh * NKEEP + (o++)] = s;
    }
}

// ---------------- sparse attention over gathered active columns --------------
// smem layout (bytes):
//   Ss   [16][1024] f32  @ 0        (65536)
//   KV   [256][68]  f32  @ 65536    (69632)
//   Qs   [16][64]   f32  @ 135168   (4096)
//   cols [1024]     int  @ 139264   (4096)
//   scan [64]       int  @ 143360   (256)
//   map  [2048]     s16  @ 143616   (4096)
//   Lm   [2048]     u8   @ 147712   (2048)
#define ATTN_SMEM 149760
__global__ __launch_bounds__(256) void attn_kernel(float* __restrict__ attn_out) {
    extern __shared__ char smc[];
    float* Ss = (float*)smc;
    float* KV = (float*)(smc + 65536);
    float* Qs = (float*)(smc + 135168);
    int* cols = (int*)(smc + 139264);
    int* scan = (int*)(smc + 143360);
    short* map = (short*)(smc + 143616);
    unsigned char* Lm = (unsigned char*)(smc + 147712);

    int bx = blockIdx.x;
    int qt = bx & 127, bh = bx >> 7;
    int qbase = qt << 4;
    size_t base = (size_t)bh * S_ * HD_;
    const float4* Qg = (const float4*)(g_q + base);
    const float4* Kg = (const float4*)(g_k + base);
    const float4* Vg = (const float4*)(g_v + base);
    int tid = threadIdx.x;
    {
        int r = tid >> 4, d4 = tid & 15;
        *(float4*)&Qs[r * 64 + d4 * 4] = Qg[(size_t)(qbase + r) * 16 + d4];
    }
    for (int l = tid; l < S_; l += 256) Lm[l] = g_land[bh * S_ + l];
    for (int c = tid; c < S_; c += 256) map[c] = -1;
    int wlo = qbase - 64; if (wlo < 0) wlo = 0;
    int whi = qbase + 79; if (whi > 2047) whi = 2047;
    int wcnt = whi - wlo + 1;
    for (int j = tid; j < wcnt; j += 256) cols[j] = wlo + j;
    // landmarks outside the window union, ascending order
    const int* lidx = g_lidx + bh * NKEEP;
    int kept[3]; int mycnt = 0;
#pragma unroll
    for (int u = 0; u < 3; u++) {
        int i = tid * 3 + u;
        if (i < NKEEP) {
            int l = lidx[i];
            if (l < wlo || l > whi) kept[mycnt++] = l;
        }
    }
    int lane = tid & 31, w = tid >> 5;
    int sc = mycnt;
#pragma unroll
    for (int o = 1; o < 32; o <<= 1) {
        int v = __shfl_up_sync(0xffffffffu, sc, o);
        if (lane >= o) sc += v;
    }
    if (lane == 31) scan[w] = sc;
    __syncthreads();
    if (tid == 0) {
        int run = 0;
        for (int i = 0; i < 8; i++) { int t = scan[i]; scan[i] = run; run += t; }
        scan[8] = run;
    }
    __syncthreads();
    int off = wcnt + scan[w] + sc - mycnt;
    for (int u = 0; u < mycnt; u++) cols[off + u] = kept[u];
    int ncols = wcnt + scan[8];
    int npad = (ncols + 255) & ~255;
    int nch = npad >> 8;
    for (int j = ncols + tid; j < npad; j += 256) cols[j] = 0;
    __syncthreads();
    for (int j = tid; j < ncols; j += 256) map[cols[j]] = (short)j;

    int rg = tid >> 6, cg = tid & 63;
    // ---- scores over gathered columns ----
    for (int ch = 0; ch < nch; ch++) {
        __syncthreads();
#pragma unroll
        for (int u = 0; u < 16; u++) {
            int fi = tid + 256 * u;
            int jj = fi >> 4, d4 = fi & 15;
            int c = cols[ch * 256 + jj];
            *(float4*)&KV[jj * 68 + d4 * 4] = Kg[(size_t)c * 16 + d4];
        }
        __syncthreads();
        float acc[4][4];
#pragma unroll
        for (int i = 0; i < 4; i++)
#pragma unroll
            for (int j = 0; j < 4; j++) acc[i][j] = 0.f;
#pragma unroll 4
        for (int d4 = 0; d4 < 16; d4++) {
            float4 q0 = *(const float4*)&Qs[(rg * 4 + 0) * 64 + d4 * 4];
            float4 q1 = *(const float4*)&Qs[(rg * 4 + 1) * 64 + d4 * 4];
            float4 q2 = *(const float4*)&Qs[(rg * 4 + 2) * 64 + d4 * 4];
            float4 q3 = *(const float4*)&Qs[(rg * 4 + 3) * 64 + d4 * 4];
            float4 k0 = *(const float4*)&KV[(cg + 0) * 68 + d4 * 4];
            float4 k1 = *(const float4*)&KV[(cg + 64) * 68 + d4 * 4];
            float4 k2 = *(const float4*)&KV[(cg + 128) * 68 + d4 * 4];
            float4 k3 = *(const float4*)&KV[(cg + 192) * 68 + d4 * 4];
            acc[0][0] += DOT4(q0, k0); acc[0][1] += DOT4(q0, k1);
            acc[0][2] += DOT4(q0, k2); acc[0][3] += DOT4(q0, k3);
            acc[1][0] += DOT4(q1, k0); acc[1][1] += DOT4(q1, k1);
            acc[1][2] += DOT4(q1, k2); acc[1][3] += DOT4(q1, k3);
            acc[2][0] += DOT4(q2, k0); acc[2][1] += DOT4(q2, k1);
            acc[2][2] += DOT4(q2, k2); acc[2][3] += DOT4(q2, k3);
            acc[3][0] += DOT4(q3, k0); acc[3][1] += DOT4(q3, k1);
            acc[3][2] += DOT4(q3, k2); acc[3][3] += DOT4(q3, k3);
        }
#pragma unroll
        for (int i = 0; i < 4; i++)
#pragma unroll
            for (int j = 0; j < 4; j++) {
                int r = rg * 4 + i;
                int jl = cg + 64 * j;
                int jg = ch * 256 + jl;
                int c = cols[jg];
                int rel = c - (qbase + r);
                bool keep = (jg < ncols) &&
                            ((rel >= -64 && rel <= 64) || (Lm[c] != 0));
                Ss[r * 1024 + jg] = keep ? acc[i][j] * 0.125f : MASKV;
            }
    }
    __syncthreads();
    // ---- softmax over compact columns; warp ty owns rows ty and ty+8 ----
    int ty = tid >> 5, tx = tid & 31;
    for (int rr = 0; rr < 2; rr++) {
        int r = ty + 8 * rr;
        float m = -3.0e38f;
        for (int j = tx; j < npad; j += 32) m = fmaxf(m, Ss[r * 1024 + j]);
#pragma unroll
        for (int o = 16; o; o >>= 1) m = fmaxf(m, __shfl_xor_sync(0xffffffffu, m, o));
        float sum = 0.f;
        for (int j = tx; j < npad; j += 32) {
            float e = __expf(Ss[r * 1024 + j] - m);
            Ss[r * 1024 + j] = e;
            sum += e;
        }
#pragma unroll
        for (int o = 16; o; o >>= 1) sum += __shfl_xor_sync(0xffffffffu, sum, o);
        float is = 1.0f / sum;
        for (int j = tx; j < npad; j += 32) Ss[r * 1024 + j] *= is;
    }
    __syncthreads();
    // ---- dense attn write (zeros where masked — exact) ----
    if (attn_out) {
        float* abase = attn_out + ((size_t)bh * S_ + qbase) * S_;
        for (int idx = tid; idx < 16 * 2048; idx += 256) {
            int r = idx >> 11, c = idx & 2047;
            int j = map[c];
            abase[(size_t)r * S_ + c] = (j >= 0) ? Ss[r * 1024 + j] : 0.f;
        }
    }
    // ---- AV over gathered columns ----
    float o00 = 0.f, o01 = 0.f, o10 = 0.f, o11 = 0.f;
    for (int ch = 0; ch < nch; ch++) {
        __syncthreads();
#pragma unroll
        for (int u = 0; u < 16; u++) {
            int fi = tid + 256 * u;
            int jj = fi >> 4, d4 = fi & 15;
            int c = cols[ch * 256 + jj];
            *(float4*)&KV[jj * 68 + d4 * 4] = Vg[(size_t)c * 16 + d4];
        }
        __syncthreads();
#pragma unroll 4
        for (int kc = 0; kc < 256; kc++) {
            int j = ch * 256 + kc;
            float p0 = Ss[ty * 1024 + j];
            float p1 = Ss[(ty + 8) * 1024 + j];
            float v0 = KV[kc * 68 + tx];
            float v1 = KV[kc * 68 + tx + 32];
            o00 += p0 * v0; o01 += p0 * v1;
            o10 += p1 * v0; o11 += p1 * v1;
        }
    }
    int b = bh >> 4, h = bh & 15;
    g_oh[(((size_t)b * S_ + qbase + ty) * H_ + h) * HD_ + tx] = o00;
    g_oh[(((size_t)b * S_ + qbase + ty) * H_ + h) * HD_ + tx + 32] = o01;
    g_oh[(((size_t)b * S_ + qbase + ty + 8) * H_ + h) * HD_ + tx] = o10;
    g_oh[(((size_t)b * S_ + qbase + ty + 8) * H_ + h) * HD_ + tx + 32] = o11;
}

// ---------------- launch ------------------------------------------------------
extern "C" void kernel_launch(void* const* d_in, const int* in_sizes, int n_in,
                              void* d_out, int out_size) {
    const float* x     = (const float*)d_in[0];
    const float* qkv_w = (const float*)d_in[1];
    const float* qkv_b = (const float*)d_in[2];
    const float* out_w = (const float*)d_in[3];
    const float* out_b = (const float*)d_in[4];
    float* out = (float*)d_out;
    const long long out_elems = (long long)B_ * S_ * D_;
    const long long attn_elems = (long long)B_ * H_ * S_ * S_;
    float* attn = ((long long)out_size >= out_elems + attn_elems) ? (out + out_elems) : (float*)0;

    cudaFuncSetAttribute(attn_kernel, cudaFuncAttributeMaxDynamicSharedMemorySize, ATTN_SMEM);
    cudaFuncSetAttribute(knn_kernel, cudaFuncAttributeMaxDynamicSharedMemorySize, KNN_SMEM);

    void* ohp = 0;
    cudaGetSymbolAddress(&ohp, g_oh);

    gemm_kernel<1><<<dim3(24, 32), 256>>>(x, qkv_w, qkv_b, (float*)0, 3072);
    stats_kernel<<<32, 256>>>(x);
    knn_kernel<<<4096, 256, KNN_SMEM>>>(x);
    tls_kernel<<<32, 256>>>();
    attn_kernel<<<4096, 256, ATTN_SMEM>>>(attn);
    gemm_kernel<0><<<dim3(8, 32), 256>>>((const float*)ohp, out_w, out_b, out, 1024);
}